// round 1
// baseline (speedup 1.0000x reference)
#include <cuda_runtime.h>
#include <cstdint>

#define SEQ    2048
#define DIMM   4096
#define NHEADS 32
#define NKVH   8
#define HD     128
#define QD     (NHEADS * HD)   // 4096
#define KVD    (NKVH * HD)     // 1024

// Scratch (no cudaMalloc allowed)
__device__ float g_q[SEQ * QD];
__device__ float g_k[SEQ * KVD];
__device__ float g_v[SEQ * KVD];
__device__ float g_att[SEQ * QD];

// ---------------------------------------------------------------------------
// Tiled SGEMM: C[M,N] = A[M,K] @ B[K,N], all row-major. 128x128x16 tile,
// 256 threads, 8x8 per-thread microtile, float4 I/O.
// Requires M%128==0, N%128==0, K%16==0 (true for all our shapes).
// ---------------------------------------------------------------------------
__global__ __launch_bounds__(256) void sgemm128(
    const float* __restrict__ A, const float* __restrict__ B,
    float* __restrict__ C, int M, int N, int K)
{
    __shared__ float As[16][128];   // transposed A tile: As[k][m]
    __shared__ float Bs[16][128];   // Bs[k][n]

    const int tid = threadIdx.x;
    const int bx = blockIdx.x, by = blockIdx.y;
    const int ty = tid >> 4;            // 0..15
    const int tx = tid & 15;            // 0..15
    const int arow = tid >> 2;          // 0..63
    const int acol = (tid & 3) << 2;    // 0,4,8,12
    const int brow = tid >> 5;          // 0..7
    const int bcol = (tid & 31) << 2;   // 0..124

    const float* Ab = A + (size_t)by * 128 * K;
    const float* Bb = B + (size_t)bx * 128;

    float acc[8][8];
#pragma unroll
    for (int i = 0; i < 8; i++)
#pragma unroll
        for (int j = 0; j < 8; j++) acc[i][j] = 0.f;

    for (int k0 = 0; k0 < K; k0 += 16) {
#pragma unroll
        for (int r = 0; r < 128; r += 64) {
            float4 v = *(const float4*)(Ab + (size_t)(arow + r) * K + k0 + acol);
            As[acol + 0][arow + r] = v.x;
            As[acol + 1][arow + r] = v.y;
            As[acol + 2][arow + r] = v.z;
            As[acol + 3][arow + r] = v.w;
        }
#pragma unroll
        for (int r = 0; r < 16; r += 8) {
            *(float4*)(&Bs[brow + r][bcol]) =
                *(const float4*)(Bb + (size_t)(k0 + brow + r) * N + bcol);
        }
        __syncthreads();

#pragma unroll
        for (int kk = 0; kk < 16; kk++) {
            float4 a0 = *(float4*)(&As[kk][ty * 8]);
            float4 a1 = *(float4*)(&As[kk][ty * 8 + 4]);
            float4 b0 = *(float4*)(&Bs[kk][tx * 8]);
            float4 b1 = *(float4*)(&Bs[kk][tx * 8 + 4]);
            float a[8] = {a0.x, a0.y, a0.z, a0.w, a1.x, a1.y, a1.z, a1.w};
            float b[8] = {b0.x, b0.y, b0.z, b0.w, b1.x, b1.y, b1.z, b1.w};
#pragma unroll
            for (int i = 0; i < 8; i++)
#pragma unroll
                for (int j = 0; j < 8; j++)
                    acc[i][j] += a[i] * b[j];
        }
        __syncthreads();
    }

    float* Cb = C + (size_t)(by * 128) * N + bx * 128;
#pragma unroll
    for (int i = 0; i < 8; i++) {
        float4 c0 = make_float4(acc[i][0], acc[i][1], acc[i][2], acc[i][3]);
        float4 c1 = make_float4(acc[i][4], acc[i][5], acc[i][6], acc[i][7]);
        *(float4*)(Cb + (size_t)(ty * 8 + i) * N + tx * 8) = c0;
        *(float4*)(Cb + (size_t)(ty * 8 + i) * N + tx * 8 + 4) = c1;
    }
}

// ---------------------------------------------------------------------------
// RoPE (interleaved pairs): t[s,h,2p],t[s,h,2p+1] rotated by (cos,sin)[s,p]
// ---------------------------------------------------------------------------
__global__ void rope_kernel(float* __restrict__ t,
                            const float* __restrict__ fc,
                            const float* __restrict__ fs,
                            int nheads, int total)
{
    int idx = blockIdx.x * blockDim.x + threadIdx.x;
    if (idx >= total) return;
    int p = idx & 63;                    // HD/2 = 64
    int h = (idx >> 6) % nheads;
    int s = idx / (64 * nheads);
    float c  = fc[s * 64 + p];
    float sn = fs[s * 64 + p];
    float* base = t + (size_t)s * nheads * HD + h * HD + 2 * p;
    float re = base[0], im = base[1];
    base[0] = re * c - im * sn;
    base[1] = re * sn + im * c;
}

// ---------------------------------------------------------------------------
// Flash attention (fp32, causal, GQA 4:1).
// Grid: (SEQ/64 q-blocks, NHEADS). 256 threads.
// Q and K stored TRANSPOSED in smem ([d][r], stride 65) -> conflict-free
// broadcast loads in the S=QK^T loop. Single KV buffer reused for K then V.
// ---------------------------------------------------------------------------
#define QTS 65
#define SSS 68
#define FLASH_SMEM_FLOATS (2 * 128 * QTS + 64 * SSS + 192)
#define FLASH_SMEM_BYTES  (FLASH_SMEM_FLOATS * 4)

__global__ __launch_bounds__(256, 2) void flash_attn(
    const float* __restrict__ Q, const float* __restrict__ K,
    const float* __restrict__ V, float* __restrict__ O)
{
    extern __shared__ float sm[];
    float* Qt   = sm;                    // [128][QTS] transposed Q tile
    float* KVs  = sm + 128 * QTS;        // K transposed [128][QTS] OR V [64][128]
    float* Ss   = sm + 2 * 128 * QTS;    // [64][SSS] score/prob tile
    float* mrow = Ss + 64 * SSS;         // [64] running max
    float* lrow = mrow + 64;             // [64] running sum
    float* arow = lrow + 64;             // [64] rescale factor

    const int tid = threadIdx.x;
    const int qb = blockIdx.x, h = blockIdx.y, kvh = h >> 2;
    const int ty4 = (tid >> 4) << 2;     // row base 0..60
    const int tx  = tid & 15;
    const int tx4 = tx << 2;             // S col base
    const int tx8 = tx << 3;             // O col base
    const float scale = 0.08838834764831845f;  // 1/sqrt(128)

    const int lr  = tid >> 5;            // 0..7  (load row)
    const int ld4 = tid & 31;            // 0..31 (load dim/4)

    // Load Q tile transposed: Qt[d][r]
#pragma unroll
    for (int rr = 0; rr < 64; rr += 8) {
        float4 v = *(const float4*)(Q + (size_t)(qb * 64 + lr + rr) * QD + h * HD + ld4 * 4);
        Qt[(ld4 * 4 + 0) * QTS + lr + rr] = v.x;
        Qt[(ld4 * 4 + 1) * QTS + lr + rr] = v.y;
        Qt[(ld4 * 4 + 2) * QTS + lr + rr] = v.z;
        Qt[(ld4 * 4 + 3) * QTS + lr + rr] = v.w;
    }
    if (tid < 64) { mrow[tid] = -1e30f; lrow[tid] = 0.f; }

    float accO[4][8];
#pragma unroll
    for (int i = 0; i < 4; i++)
#pragma unroll
        for (int j = 0; j < 8; j++) accO[i][j] = 0.f;

    __syncthreads();

    for (int kb = 0; kb <= qb; kb++) {
        // ---- load K block transposed into KVs ----
#pragma unroll
        for (int rr = 0; rr < 64; rr += 8) {
            float4 v = *(const float4*)(K + (size_t)(kb * 64 + lr + rr) * KVD + kvh * HD + ld4 * 4);
            KVs[(ld4 * 4 + 0) * QTS + lr + rr] = v.x;
            KVs[(ld4 * 4 + 1) * QTS + lr + rr] = v.y;
            KVs[(ld4 * 4 + 2) * QTS + lr + rr] = v.z;
            KVs[(ld4 * 4 + 3) * QTS + lr + rr] = v.w;
        }
        __syncthreads();

        // ---- S = Q @ K^T (64x64), each thread 4x4 ----
        float sreg[4][4];
#pragma unroll
        for (int i = 0; i < 4; i++)
#pragma unroll
            for (int j = 0; j < 4; j++) sreg[i][j] = 0.f;

#pragma unroll 4
        for (int d = 0; d < HD; d++) {
            float qv[4], kv[4];
#pragma unroll
            for (int i = 0; i < 4; i++) qv[i] = Qt[d * QTS + ty4 + i];
#pragma unroll
            for (int j = 0; j < 4; j++) kv[j] = KVs[d * QTS + tx4 + j];
#pragma unroll
            for (int i = 0; i < 4; i++)
#pragma unroll
                for (int j = 0; j < 4; j++)
                    sreg[i][j] += qv[i] * kv[j];
        }
        const bool diag = (kb == qb);
#pragma unroll
        for (int i = 0; i < 4; i++)
#pragma unroll
            for (int j = 0; j < 4; j++) {
                float s = sreg[i][j] * scale;
                if (diag && (tx4 + j) > (ty4 + i)) s = -1e30f;
                Ss[(ty4 + i) * SSS + tx4 + j] = s;
            }
        __syncthreads();   // S done, K reads done -> KVs reusable

        // ---- load V block (row-major) into KVs; softmax concurrently ----
#pragma unroll
        for (int rr = 0; rr < 64; rr += 8) {
            *(float4*)(KVs + (size_t)(lr + rr) * HD + ld4 * 4) =
                *(const float4*)(V + (size_t)(kb * 64 + lr + rr) * KVD + kvh * HD + ld4 * 4);
        }
        if (tid < 64) {
            const int r = tid;
            float mold = mrow[r];
            float mx = mold;
#pragma unroll 8
            for (int c = 0; c < 64; c++) mx = fmaxf(mx, Ss[r * SSS + c]);
            float alpha = __expf(mold - mx);
            float sum = 0.f;
#pragma unroll 8
            for (int c = 0; c < 64; c++) {
                float p = __expf(Ss[r * SSS + c] - mx);
                Ss[r * SSS + c] = p;
                sum += p;
            }
            mrow[r] = mx;
            lrow[r] = lrow[r] * alpha + sum;
            arow[r] = alpha;
        }
        __syncthreads();

        // ---- O = O*alpha + P @ V ----
        float al[4];
#pragma unroll
        for (int i = 0; i < 4; i++) al[i] = arow[ty4 + i];
#pragma unroll
        for (int i = 0; i < 4; i++)
#pragma unroll
            for (int j = 0; j < 8; j++) accO[i][j] *= al[i];

#pragma unroll 4
        for (int kk = 0; kk < 64; kk++) {
            float p0 = Ss[(ty4 + 0) * SSS + kk];
            float p1 = Ss[(ty4 + 1) * SSS + kk];
            float p2 = Ss[(ty4 + 2) * SSS + kk];
            float p3 = Ss[(ty4 + 3) * SSS + kk];
            float4 v0 = *(float4*)(KVs + (size_t)kk * HD + tx8);
            float4 v1 = *(float4*)(KVs + (size_t)kk * HD + tx8 + 4);
            float vv[8] = {v0.x, v0.y, v0.z, v0.w, v1.x, v1.y, v1.z, v1.w};
#pragma unroll
            for (int j = 0; j < 8; j++) {
                accO[0][j] += p0 * vv[j];
                accO[1][j] += p1 * vv[j];
                accO[2][j] += p2 * vv[j];
                accO[3][j] += p3 * vv[j];
            }
        }
        __syncthreads();   // before next K load overwrites KVs
    }

    // ---- epilogue: normalize + store, layout O[s][h*128+d] ----
#pragma unroll
    for (int i = 0; i < 4; i++) {
        float inv = 1.f / lrow[ty4 + i];
        float4 o0 = make_float4(accO[i][0] * inv, accO[i][1] * inv,
                                accO[i][2] * inv, accO[i][3] * inv);
        float4 o1 = make_float4(accO[i][4] * inv, accO[i][5] * inv,
                                accO[i][6] * inv, accO[i][7] * inv);
        float* op = O + (size_t)(qb * 64 + ty4 + i) * QD + h * HD + tx8;
        *(float4*)(op) = o0;
        *(float4*)(op + 4) = o1;
    }
}

// ---------------------------------------------------------------------------
// Launch
// ---------------------------------------------------------------------------
extern "C" void kernel_launch(void* const* d_in, const int* in_sizes, int n_in,
                              void* d_out, int out_size)
{
    const float* x  = (const float*)d_in[0];
    const float* wq = (const float*)d_in[1];
    const float* wk = (const float*)d_in[2];
    const float* wv = (const float*)d_in[3];
    const float* wo = (const float*)d_in[4];
    const float* fc = (const float*)d_in[5];
    const float* fs = (const float*)d_in[6];
    // d_in[7] = mask (unused; causal mask applied analytically)
    float* out = (float*)d_out;

    float *q, *k, *v, *att;
    cudaGetSymbolAddress((void**)&q,   g_q);
    cudaGetSymbolAddress((void**)&k,   g_k);
    cudaGetSymbolAddress((void**)&v,   g_v);
    cudaGetSymbolAddress((void**)&att, g_att);

    cudaFuncSetAttribute(flash_attn,
                         cudaFuncAttributeMaxDynamicSharedMemorySize,
                         FLASH_SMEM_BYTES);

    // QKV projections
    sgemm128<<<dim3(QD / 128,  SEQ / 128), 256>>>(x, wq, q, SEQ, QD,  DIMM);
    sgemm128<<<dim3(KVD / 128, SEQ / 128), 256>>>(x, wk, k, SEQ, KVD, DIMM);
    sgemm128<<<dim3(KVD / 128, SEQ / 128), 256>>>(x, wv, v, SEQ, KVD, DIMM);

    // RoPE
    int totq = SEQ * NHEADS * (HD / 2);
    int totk = SEQ * NKVH * (HD / 2);
    rope_kernel<<<(totq + 255) / 256, 256>>>(q, fc, fs, NHEADS, totq);
    rope_kernel<<<(totk + 255) / 256, 256>>>(k, fc, fs, NKVH, totk);

    // Fused causal attention
    flash_attn<<<dim3(SEQ / 64, NHEADS), 256, FLASH_SMEM_BYTES>>>(q, k, v, att);

    // Output projection
    sgemm128<<<dim3(DIMM / 128, SEQ / 128), 256>>>(att, wo, out, SEQ, DIMM, QD);
}

// round 4
// speedup vs baseline: 2.0815x; 2.0815x over previous
#include <cuda_runtime.h>
#include <cstdint>

#define SEQ    2048
#define DIMM   4096
#define NHEADS 32
#define NKVH   8
#define HD     128
#define QD     (NHEADS * HD)   // 4096
#define KVD    (NKVH * HD)     // 1024

// Scratch (no cudaMalloc allowed)
__device__ float g_q[SEQ * QD];
__device__ float g_k[SEQ * KVD];
__device__ float g_v[SEQ * KVD];
__device__ float g_att[SEQ * QD];

// ===========================================================================
// TF32 tensor-core GEMM: C[M,N] = A[M,K] @ B[K,N], row-major.
// 128x128x32 CTA tile, 256 threads = 8 warps (2x4), warp tile 64x32,
// mma.sync.m16n8k8 tf32, cp.async 2-stage double buffering.
// Requires M%128==0, N%128==0, K%32==0.
// ===========================================================================
#define BM 128
#define BN 128
#define BK 32
#define ASTRIDE 36    // (BK+4): frag-load banks = 4*g + tg  -> conflict-free
#define BSTRIDE 136   // (BN+8): frag-load banks = 8*tg + g -> conflict-free
#define STAGE_FLOATS (BM * ASTRIDE + BK * BSTRIDE)   // 4608 + 4352 = 8960
#define GEMM_SMEM_BYTES (2 * STAGE_FLOATS * 4)       // 71680

__device__ __forceinline__ uint32_t f2tf32(float x) {
    uint32_t r;
    asm("cvt.rna.tf32.f32 %0, %1;" : "=r"(r) : "f"(x));
    return r;
}

__device__ __forceinline__ void mma_tf32(float* c, const uint32_t* a, const uint32_t* b) {
    asm volatile(
        "mma.sync.aligned.m16n8k8.row.col.f32.tf32.tf32.f32 "
        "{%0,%1,%2,%3}, {%4,%5,%6,%7}, {%8,%9}, {%0,%1,%2,%3};\n"
        : "+f"(c[0]), "+f"(c[1]), "+f"(c[2]), "+f"(c[3])
        : "r"(a[0]), "r"(a[1]), "r"(a[2]), "r"(a[3]),
          "r"(b[0]), "r"(b[1]));
}

__device__ __forceinline__ void cp_async16(void* smem_dst, const void* gmem_src) {
    uint32_t dst = (uint32_t)__cvta_generic_to_shared(smem_dst);
    asm volatile("cp.async.cg.shared.global [%0], [%1], 16;\n"
                 :: "r"(dst), "l"(gmem_src));
}

__global__ __launch_bounds__(256, 1) void gemm_tf32(
    const float* __restrict__ A, const float* __restrict__ B,
    float* __restrict__ C, int M, int N, int K)
{
    extern __shared__ float sm[];

    const int tid = threadIdx.x;
    const int bx = blockIdx.x, by = blockIdx.y;

    // staging maps
    const int arow0 = tid >> 3;          // 0..31
    const int acol4 = (tid & 7) << 2;    // 0,4,..28
    const int brow0 = tid >> 5;          // 0..7
    const int bcol4 = (tid & 31) << 2;   // 0,4,..124

    // compute maps
    const int lane = tid & 31;
    const int warp = tid >> 5;
    const int wr = warp >> 2;            // 0..1
    const int wc = warp & 3;             // 0..3
    const int g  = lane >> 2;            // 0..7
    const int tg = lane & 3;             // 0..3
    const int morg = wr * 64;
    const int norg = wc * 32;

    const float* Ab = A + (size_t)by * BM * K;
    const float* Bb = B + (size_t)bx * BN;

    float acc[4][4][4];
#pragma unroll
    for (int mi = 0; mi < 4; mi++)
#pragma unroll
        for (int ni = 0; ni < 4; ni++)
#pragma unroll
            for (int r = 0; r < 4; r++) acc[mi][ni][r] = 0.f;

    const int nk = K / BK;

    // issue loads for one stage
    auto load_stage = [&](int s, int k0) {
        float* As_ = sm + s * STAGE_FLOATS;
        float* Bs_ = As_ + BM * ASTRIDE;
#pragma unroll
        for (int r = 0; r < BM; r += 32)
            cp_async16(&As_[(arow0 + r) * ASTRIDE + acol4],
                       Ab + (size_t)(arow0 + r) * K + k0 + acol4);
#pragma unroll
        for (int r = 0; r < BK; r += 8)
            cp_async16(&Bs_[(brow0 + r) * BSTRIDE + bcol4],
                       Bb + (size_t)(k0 + brow0 + r) * N + bcol4);
        asm volatile("cp.async.commit_group;\n");
    };

    load_stage(0, 0);

    for (int kt = 0; kt < nk; kt++) {
        asm volatile("cp.async.wait_group 0;\n");
        __syncthreads();
        if (kt + 1 < nk) load_stage((kt + 1) & 1, (kt + 1) * BK);

        const float* As_ = sm + (kt & 1) * STAGE_FLOATS;
        const float* Bs_ = As_ + BM * ASTRIDE;

#pragma unroll
        for (int k8 = 0; k8 < BK; k8 += 8) {
            uint32_t af[4][4], bf[4][2];
#pragma unroll
            for (int mi = 0; mi < 4; mi++) {
                const int r = morg + mi * 16 + g;
                af[mi][0] = f2tf32(As_[(r)     * ASTRIDE + k8 + tg]);
                af[mi][1] = f2tf32(As_[(r + 8) * ASTRIDE + k8 + tg]);
                af[mi][2] = f2tf32(As_[(r)     * ASTRIDE + k8 + tg + 4]);
                af[mi][3] = f2tf32(As_[(r + 8) * ASTRIDE + k8 + tg + 4]);
            }
#pragma unroll
            for (int ni = 0; ni < 4; ni++) {
                const int c = norg + ni * 8 + g;
                bf[ni][0] = f2tf32(Bs_[(k8 + tg)     * BSTRIDE + c]);
                bf[ni][1] = f2tf32(Bs_[(k8 + tg + 4) * BSTRIDE + c]);
            }
#pragma unroll
            for (int mi = 0; mi < 4; mi++)
#pragma unroll
                for (int ni = 0; ni < 4; ni++)
                    mma_tf32(acc[mi][ni], af[mi], bf[ni]);
        }
    }

    // epilogue
    float* Cb = C + (size_t)(by * BM) * N + bx * BN;
#pragma unroll
    for (int mi = 0; mi < 4; mi++) {
#pragma unroll
        for (int ni = 0; ni < 4; ni++) {
            const int r0 = morg + mi * 16 + g;
            const int c0 = norg + ni * 8 + tg * 2;
            *(float2*)(&Cb[(size_t)r0 * N + c0]) =
                make_float2(acc[mi][ni][0], acc[mi][ni][1]);
            *(float2*)(&Cb[(size_t)(r0 + 8) * N + c0]) =
                make_float2(acc[mi][ni][2], acc[mi][ni][3]);
        }
    }
}

// ---------------------------------------------------------------------------
// RoPE (interleaved pairs)
// ---------------------------------------------------------------------------
__global__ void rope_kernel(float* __restrict__ t,
                            const float* __restrict__ fc,
                            const float* __restrict__ fs,
                            int nheads, int total)
{
    int idx = blockIdx.x * blockDim.x + threadIdx.x;
    if (idx >= total) return;
    int p = idx & 63;
    int h = (idx >> 6) % nheads;
    int s = idx / (64 * nheads);
    float c  = fc[s * 64 + p];
    float sn = fs[s * 64 + p];
    float* base = t + (size_t)s * nheads * HD + h * HD + 2 * p;
    float re = base[0], im = base[1];
    base[0] = re * c - im * sn;
    base[1] = re * sn + im * c;
}

// ---------------------------------------------------------------------------
// Flash attention (fp32, causal, GQA 4:1)
// ---------------------------------------------------------------------------
#define QTS 65
#define SSS 68
#define FLASH_SMEM_FLOATS (2 * 128 * QTS + 64 * SSS + 192)
#define FLASH_SMEM_BYTES  (FLASH_SMEM_FLOATS * 4)

__global__ __launch_bounds__(256, 2) void flash_attn(
    const float* __restrict__ Q, const float* __restrict__ K,
    const float* __restrict__ V, float* __restrict__ O)
{
    extern __shared__ float sm[];
    float* Qt   = sm;
    float* KVs  = sm + 128 * QTS;
    float* Ss   = sm + 2 * 128 * QTS;
    float* mrow = Ss + 64 * SSS;
    float* lrow = mrow + 64;
    float* arow = lrow + 64;

    const int tid = threadIdx.x;
    const int qb = blockIdx.x, h = blockIdx.y, kvh = h >> 2;
    const int ty4 = (tid >> 4) << 2;
    const int tx  = tid & 15;
    const int tx4 = tx << 2;
    const int tx8 = tx << 3;
    const float scale = 0.08838834764831845f;

    const int lr  = tid >> 5;
    const int ld4 = tid & 31;

#pragma unroll
    for (int rr = 0; rr < 64; rr += 8) {
        float4 v = *(const float4*)(Q + (size_t)(qb * 64 + lr + rr) * QD + h * HD + ld4 * 4);
        Qt[(ld4 * 4 + 0) * QTS + lr + rr] = v.x;
        Qt[(ld4 * 4 + 1) * QTS + lr + rr] = v.y;
        Qt[(ld4 * 4 + 2) * QTS + lr + rr] = v.z;
        Qt[(ld4 * 4 + 3) * QTS + lr + rr] = v.w;
    }
    if (tid < 64) { mrow[tid] = -1e30f; lrow[tid] = 0.f; }

    float accO[4][8];
#pragma unroll
    for (int i = 0; i < 4; i++)
#pragma unroll
        for (int j = 0; j < 8; j++) accO[i][j] = 0.f;

    __syncthreads();

    for (int kb = 0; kb <= qb; kb++) {
#pragma unroll
        for (int rr = 0; rr < 64; rr += 8) {
            float4 v = *(const float4*)(K + (size_t)(kb * 64 + lr + rr) * KVD + kvh * HD + ld4 * 4);
            KVs[(ld4 * 4 + 0) * QTS + lr + rr] = v.x;
            KVs[(ld4 * 4 + 1) * QTS + lr + rr] = v.y;
            KVs[(ld4 * 4 + 2) * QTS + lr + rr] = v.z;
            KVs[(ld4 * 4 + 3) * QTS + lr + rr] = v.w;
        }
        __syncthreads();

        float sreg[4][4];
#pragma unroll
        for (int i = 0; i < 4; i++)
#pragma unroll
            for (int j = 0; j < 4; j++) sreg[i][j] = 0.f;

#pragma unroll 4
        for (int d = 0; d < HD; d++) {
            float qv[4], kv[4];
#pragma unroll
            for (int i = 0; i < 4; i++) qv[i] = Qt[d * QTS + ty4 + i];
#pragma unroll
            for (int j = 0; j < 4; j++) kv[j] = KVs[d * QTS + tx4 + j];
#pragma unroll
            for (int i = 0; i < 4; i++)
#pragma unroll
                for (int j = 0; j < 4; j++)
                    sreg[i][j] += qv[i] * kv[j];
        }
        const bool diag = (kb == qb);
#pragma unroll
        for (int i = 0; i < 4; i++)
#pragma unroll
            for (int j = 0; j < 4; j++) {
                float s = sreg[i][j] * scale;
                if (diag && (tx4 + j) > (ty4 + i)) s = -1e30f;
                Ss[(ty4 + i) * SSS + tx4 + j] = s;
            }
        __syncthreads();

#pragma unroll
        for (int rr = 0; rr < 64; rr += 8) {
            *(float4*)(KVs + (size_t)(lr + rr) * HD + ld4 * 4) =
                *(const float4*)(V + (size_t)(kb * 64 + lr + rr) * KVD + kvh * HD + ld4 * 4);
        }
        if (tid < 64) {
            const int r = tid;
            float mold = mrow[r];
            float mx = mold;
#pragma unroll 8
            for (int c = 0; c < 64; c++) mx = fmaxf(mx, Ss[r * SSS + c]);
            float alpha = __expf(mold - mx);
            float sum = 0.f;
#pragma unroll 8
            for (int c = 0; c < 64; c++) {
                float p = __expf(Ss[r * SSS + c] - mx);
                Ss[r * SSS + c] = p;
                sum += p;
            }
            mrow[r] = mx;
            lrow[r] = lrow[r] * alpha + sum;
            arow[r] = alpha;
        }
        __syncthreads();

        float al[4];
#pragma unroll
        for (int i = 0; i < 4; i++) al[i] = arow[ty4 + i];
#pragma unroll
        for (int i = 0; i < 4; i++)
#pragma unroll
            for (int j = 0; j < 8; j++) accO[i][j] *= al[i];

#pragma unroll 4
        for (int kk = 0; kk < 64; kk++) {
            float p0 = Ss[(ty4 + 0) * SSS + kk];
            float p1 = Ss[(ty4 + 1) * SSS + kk];
            float p2 = Ss[(ty4 + 2) * SSS + kk];
            float p3 = Ss[(ty4 + 3) * SSS + kk];
            float4 v0 = *(float4*)(KVs + (size_t)kk * HD + tx8);
            float4 v1 = *(float4*)(KVs + (size_t)kk * HD + tx8 + 4);
            float vv[8] = {v0.x, v0.y, v0.z, v0.w, v1.x, v1.y, v1.z, v1.w};
#pragma unroll
            for (int j = 0; j < 8; j++) {
                accO[0][j] += p0 * vv[j];
                accO[1][j] += p1 * vv[j];
                accO[2][j] += p2 * vv[j];
                accO[3][j] += p3 * vv[j];
            }
        }
        __syncthreads();
    }

#pragma unroll
    for (int i = 0; i < 4; i++) {
        float inv = 1.f / lrow[ty4 + i];
        float4 o0 = make_float4(accO[i][0] * inv, accO[i][1] * inv,
                                accO[i][2] * inv, accO[i][3] * inv);
        float4 o1 = make_float4(accO[i][4] * inv, accO[i][5] * inv,
                                accO[i][6] * inv, accO[i][7] * inv);
        float* op = O + (size_t)(qb * 64 + ty4 + i) * QD + h * HD + tx8;
        *(float4*)(op) = o0;
        *(float4*)(op + 4) = o1;
    }
}

// ---------------------------------------------------------------------------
// Launch
// ---------------------------------------------------------------------------
extern "C" void kernel_launch(void* const* d_in, const int* in_sizes, int n_in,
                              void* d_out, int out_size)
{
    (void)in_sizes; (void)n_in; (void)out_size;
    const float* x  = (const float*)d_in[0];
    const float* wq = (const float*)d_in[1];
    const float* wk = (const float*)d_in[2];
    const float* wv = (const float*)d_in[3];
    const float* wo = (const float*)d_in[4];
    const float* fc = (const float*)d_in[5];
    const float* fs = (const float*)d_in[6];
    float* out = (float*)d_out;

    float *q, *k, *v, *att;
    cudaGetSymbolAddress((void**)&q,   g_q);
    cudaGetSymbolAddress((void**)&k,   g_k);
    cudaGetSymbolAddress((void**)&v,   g_v);
    cudaGetSymbolAddress((void**)&att, g_att);

    cudaFuncSetAttribute(gemm_tf32,
                         cudaFuncAttributeMaxDynamicSharedMemorySize,
                         GEMM_SMEM_BYTES);
    cudaFuncSetAttribute(flash_attn,
                         cudaFuncAttributeMaxDynamicSharedMemorySize,
                         FLASH_SMEM_BYTES);

    // QKV projections (tf32 tensor cores)
    gemm_tf32<<<dim3(QD / BN,  SEQ / BM), 256, GEMM_SMEM_BYTES>>>(x, wq, q, SEQ, QD,  DIMM);
    gemm_tf32<<<dim3(KVD / BN, SEQ / BM), 256, GEMM_SMEM_BYTES>>>(x, wk, k, SEQ, KVD, DIMM);
    gemm_tf32<<<dim3(KVD / BN, SEQ / BM), 256, GEMM_SMEM_BYTES>>>(x, wv, v, SEQ, KVD, DIMM);

    // RoPE
    int totq = SEQ * NHEADS * (HD / 2);
    int totk = SEQ * NKVH * (HD / 2);
    rope_kernel<<<(totq + 255) / 256, 256>>>(q, fc, fs, NHEADS, totq);
    rope_kernel<<<(totk + 255) / 256, 256>>>(k, fc, fs, NKVH, totk);

    // Fused causal attention
    flash_attn<<<dim3(SEQ / 64, NHEADS), 256, FLASH_SMEM_BYTES>>>(q, k, v, att);

    // Output projection
    gemm_tf32<<<dim3(DIMM / BN, SEQ / BM), 256, GEMM_SMEM_BYTES>>>(att, wo, out, SEQ, DIMM, QD);
}

// round 6
// speedup vs baseline: 3.0414x; 1.4612x over previous
#include <cuda_runtime.h>
#include <cstdint>

#define SEQ    2048
#define DIMM   4096
#define NHEADS 32
#define NKVH   8
#define HD     128
#define QD     (NHEADS * HD)   // 4096
#define KVD    (NKVH * HD)     // 1024

// Scratch (no cudaMalloc allowed)
__device__ float g_q[SEQ * QD];
__device__ float g_k[SEQ * KVD];
__device__ float g_v[SEQ * KVD];
__device__ float g_att[SEQ * QD];

__device__ __forceinline__ uint32_t f2tf32(float x) {
    uint32_t r;
    asm("cvt.rna.tf32.f32 %0, %1;" : "=r"(r) : "f"(x));
    return r;
}

__device__ __forceinline__ void mma_tf32(float* c, const uint32_t* a, const uint32_t* b) {
    asm volatile(
        "mma.sync.aligned.m16n8k8.row.col.f32.tf32.tf32.f32 "
        "{%0,%1,%2,%3}, {%4,%5,%6,%7}, {%8,%9}, {%0,%1,%2,%3};\n"
        : "+f"(c[0]), "+f"(c[1]), "+f"(c[2]), "+f"(c[3])
        : "r"(a[0]), "r"(a[1]), "r"(a[2]), "r"(a[3]),
          "r"(b[0]), "r"(b[1]));
}

__device__ __forceinline__ void cp_async16(void* smem_dst, const void* gmem_src) {
    uint32_t dst = (uint32_t)__cvta_generic_to_shared(smem_dst);
    asm volatile("cp.async.cg.shared.global [%0], [%1], 16;\n"
                 :: "r"(dst), "l"(gmem_src));
}

// ===========================================================================
// TF32 tensor-core GEMM (unchanged from R4)
// ===========================================================================
#define BM 128
#define BN 128
#define BK 32
#define ASTRIDE 36
#define BSTRIDE 136
#define STAGE_FLOATS (BM * ASTRIDE + BK * BSTRIDE)
#define GEMM_SMEM_BYTES (2 * STAGE_FLOATS * 4)

__global__ __launch_bounds__(256, 1) void gemm_tf32(
    const float* __restrict__ A, const float* __restrict__ B,
    float* __restrict__ C, int M, int N, int K)
{
    extern __shared__ float sm[];

    const int tid = threadIdx.x;
    const int bx = blockIdx.x, by = blockIdx.y;

    const int arow0 = tid >> 3;
    const int acol4 = (tid & 7) << 2;
    const int brow0 = tid >> 5;
    const int bcol4 = (tid & 31) << 2;

    const int lane = tid & 31;
    const int warp = tid >> 5;
    const int wr = warp >> 2;
    const int wc = warp & 3;
    const int g  = lane >> 2;
    const int tg = lane & 3;
    const int morg = wr * 64;
    const int norg = wc * 32;

    const float* Ab = A + (size_t)by * BM * K;
    const float* Bb = B + (size_t)bx * BN;

    float acc[4][4][4];
#pragma unroll
    for (int mi = 0; mi < 4; mi++)
#pragma unroll
        for (int ni = 0; ni < 4; ni++)
#pragma unroll
            for (int r = 0; r < 4; r++) acc[mi][ni][r] = 0.f;

    const int nk = K / BK;

    auto load_stage = [&](int s, int k0) {
        float* As_ = sm + s * STAGE_FLOATS;
        float* Bs_ = As_ + BM * ASTRIDE;
#pragma unroll
        for (int r = 0; r < BM; r += 32)
            cp_async16(&As_[(arow0 + r) * ASTRIDE + acol4],
                       Ab + (size_t)(arow0 + r) * K + k0 + acol4);
#pragma unroll
        for (int r = 0; r < BK; r += 8)
            cp_async16(&Bs_[(brow0 + r) * BSTRIDE + bcol4],
                       Bb + (size_t)(k0 + brow0 + r) * N + bcol4);
        asm volatile("cp.async.commit_group;\n");
    };

    load_stage(0, 0);

    for (int kt = 0; kt < nk; kt++) {
        asm volatile("cp.async.wait_group 0;\n");
        __syncthreads();
        if (kt + 1 < nk) load_stage((kt + 1) & 1, (kt + 1) * BK);

        const float* As_ = sm + (kt & 1) * STAGE_FLOATS;
        const float* Bs_ = As_ + BM * ASTRIDE;

#pragma unroll
        for (int k8 = 0; k8 < BK; k8 += 8) {
            uint32_t af[4][4], bf[4][2];
#pragma unroll
            for (int mi = 0; mi < 4; mi++) {
                const int r = morg + mi * 16 + g;
                af[mi][0] = f2tf32(As_[(r)     * ASTRIDE + k8 + tg]);
                af[mi][1] = f2tf32(As_[(r + 8) * ASTRIDE + k8 + tg]);
                af[mi][2] = f2tf32(As_[(r)     * ASTRIDE + k8 + tg + 4]);
                af[mi][3] = f2tf32(As_[(r + 8) * ASTRIDE + k8 + tg + 4]);
            }
#pragma unroll
            for (int ni = 0; ni < 4; ni++) {
                const int c = norg + ni * 8 + g;
                bf[ni][0] = f2tf32(Bs_[(k8 + tg)     * BSTRIDE + c]);
                bf[ni][1] = f2tf32(Bs_[(k8 + tg + 4) * BSTRIDE + c]);
            }
#pragma unroll
            for (int mi = 0; mi < 4; mi++)
#pragma unroll
                for (int ni = 0; ni < 4; ni++)
                    mma_tf32(acc[mi][ni], af[mi], bf[ni]);
        }
    }

    float* Cb = C + (size_t)(by * BM) * N + bx * BN;
#pragma unroll
    for (int mi = 0; mi < 4; mi++) {
#pragma unroll
        for (int ni = 0; ni < 4; ni++) {
            const int r0 = morg + mi * 16 + g;
            const int c0 = norg + ni * 8 + tg * 2;
            *(float2*)(&Cb[(size_t)r0 * N + c0]) =
                make_float2(acc[mi][ni][0], acc[mi][ni][1]);
            *(float2*)(&Cb[(size_t)(r0 + 8) * N + c0]) =
                make_float2(acc[mi][ni][2], acc[mi][ni][3]);
        }
    }
}

// ---------------------------------------------------------------------------
// RoPE (interleaved pairs)
// ---------------------------------------------------------------------------
__global__ void rope_kernel(float* __restrict__ t,
                            const float* __restrict__ fc,
                            const float* __restrict__ fs,
                            int nheads, int total)
{
    int idx = blockIdx.x * blockDim.x + threadIdx.x;
    if (idx >= total) return;
    int p = idx & 63;
    int h = (idx >> 6) % nheads;
    int s = idx / (64 * nheads);
    float c  = fc[s * 64 + p];
    float sn = fs[s * 64 + p];
    float* base = t + (size_t)s * nheads * HD + h * HD + 2 * p;
    float re = base[0], im = base[1];
    base[0] = re * c - im * sn;
    base[1] = re * sn + im * c;
}

// ===========================================================================
// Tensor-core flash attention (causal, GQA 4:1).
// 64x64 tiles. QK^T: single tf32 mma. P@V: V split hi+lo tf32 (2 mma) for
// near-fp32 PV accuracy. Online softmax in smem (64 threads).
// Smem strides: Q/K 132 (=4 mod 32), V 136 (=8 mod 32), S 68 (=4 mod 32)
// -> all fragment LDS conflict-free. 86.8 KB smem, 2 CTAs/SM.
// ===========================================================================
#define QSTR 132
#define VSTR 136
#define SSTR 68
#define FA_Q_FLOATS   (64 * QSTR)             // 8448
#define FA_KV_FLOATS  (64 * VSTR)             // 8704 (fits K@132 and V@136)
#define FA_S_FLOATS   (64 * SSTR)             // 4352
#define FA_SMEM_FLOATS (FA_Q_FLOATS + FA_KV_FLOATS + FA_S_FLOATS + 192)
#define FA_SMEM_BYTES  (FA_SMEM_FLOATS * 4)   // 86784

__global__ __launch_bounds__(256, 2) void flash_attn_tc(
    const float* __restrict__ Q, const float* __restrict__ K,
    const float* __restrict__ V, float* __restrict__ O)
{
    extern __shared__ float sm[];
    float* Qt   = sm;                          // [64][QSTR]
    float* KVs  = sm + FA_Q_FLOATS;            // K:[64][QSTR] or V:[64][VSTR]
    float* Ss   = KVs + FA_KV_FLOATS;          // [64][SSTR]
    float* mrow = Ss + FA_S_FLOATS;            // [64]
    float* lrow = mrow + 64;
    float* arow = lrow + 64;

    const int tid  = threadIdx.x;
    const int qb   = blockIdx.x, h = blockIdx.y, kvh = h >> 2;
    const int lane = tid & 31;
    const int warp = tid >> 5;
    const int g    = lane >> 2;     // 0..7
    const int tg   = lane & 3;      // 0..3
    const int mi   = warp & 3;      // m tile 0..3 (16 rows each)
    const int nj   = warp >> 1 >> 1;// warp>>2: 0..1
    const int lr   = tid >> 5;      // load row 0..7
    const int ld4  = (tid & 31) << 2;
    const float scale = 0.08838834764831845f;  // 1/sqrt(128)

    const int mrow0 = mi * 16 + g;             // this lane's first row

    // ---- load Q tile (prescaled) ----
#pragma unroll
    for (int rr = 0; rr < 64; rr += 8) {
        float4 v = *(const float4*)(Q + (size_t)(qb * 64 + lr + rr) * QD + h * HD + ld4);
        v.x *= scale; v.y *= scale; v.z *= scale; v.w *= scale;
        *(float4*)(Qt + (lr + rr) * QSTR + ld4) = v;
    }
    if (tid < 64) { mrow[tid] = -1e30f; lrow[tid] = 0.f; }

    float accO[8][4];
#pragma unroll
    for (int ns = 0; ns < 8; ns++)
#pragma unroll
        for (int r = 0; r < 4; r++) accO[ns][r] = 0.f;

    __syncthreads();

    for (int kb = 0; kb <= qb; kb++) {
        // ---- load K tile [64][QSTR] ----
#pragma unroll
        for (int rr = 0; rr < 64; rr += 8) {
            *(float4*)(KVs + (lr + rr) * QSTR + ld4) =
                *(const float4*)(K + (size_t)(kb * 64 + lr + rr) * KVD + kvh * HD + ld4);
        }
        __syncthreads();

        // ---- S = Qs @ K^T : warp tile 16x32 at (mi*16, nj*32) ----
        float cS[4][4];
#pragma unroll
        for (int ns = 0; ns < 4; ns++)
#pragma unroll
            for (int r = 0; r < 4; r++) cS[ns][r] = 0.f;

#pragma unroll
        for (int k8 = 0; k8 < HD; k8 += 8) {
            uint32_t a[4];
            a[0] = f2tf32(Qt[(mrow0)     * QSTR + k8 + tg]);
            a[1] = f2tf32(Qt[(mrow0 + 8) * QSTR + k8 + tg]);
            a[2] = f2tf32(Qt[(mrow0)     * QSTR + k8 + tg + 4]);
            a[3] = f2tf32(Qt[(mrow0 + 8) * QSTR + k8 + tg + 4]);
#pragma unroll
            for (int ns = 0; ns < 4; ns++) {
                const int c = nj * 32 + ns * 8 + g;
                uint32_t b[2];
                b[0] = f2tf32(KVs[c * QSTR + k8 + tg]);
                b[1] = f2tf32(KVs[c * QSTR + k8 + tg + 4]);
                mma_tf32(cS[ns], a, b);
            }
        }
        // write S tile to smem
#pragma unroll
        for (int ns = 0; ns < 4; ns++) {
            const int cc = nj * 32 + ns * 8 + 2 * tg;
            *(float2*)(Ss + (mrow0)     * SSTR + cc) = make_float2(cS[ns][0], cS[ns][1]);
            *(float2*)(Ss + (mrow0 + 8) * SSTR + cc) = make_float2(cS[ns][2], cS[ns][3]);
        }
        __syncthreads();

        // ---- load V tile [64][VSTR]; softmax on 64 threads ----
#pragma unroll
        for (int rr = 0; rr < 64; rr += 8) {
            *(float4*)(KVs + (lr + rr) * VSTR + ld4) =
                *(const float4*)(V + (size_t)(kb * 64 + lr + rr) * KVD + kvh * HD + ld4);
        }
        if (tid < 64) {
            const int r = tid;
            const int lim = (kb == qb) ? (r + 1) : 64;
            float mold = mrow[r];
            float mx = mold;
            for (int c = 0; c < lim; c++) mx = fmaxf(mx, Ss[r * SSTR + c]);
            float alpha = __expf(mold - mx);
            float sum = 0.f;
            for (int c = 0; c < lim; c++) {
                float p = __expf(Ss[r * SSTR + c] - mx);
                Ss[r * SSTR + c] = p;
                sum += p;
            }
            for (int c = lim; c < 64; c++) Ss[r * SSTR + c] = 0.f;
            mrow[r] = mx;
            lrow[r] = lrow[r] * alpha + sum;
            arow[r] = alpha;
        }
        __syncthreads();

        // ---- O = O*alpha + P @ V : warp tile 16x64 at (mi*16, nj*64) ----
        {
            float a0 = arow[mrow0], a1 = arow[mrow0 + 8];
#pragma unroll
            for (int ns = 0; ns < 8; ns++) {
                accO[ns][0] *= a0; accO[ns][1] *= a0;
                accO[ns][2] *= a1; accO[ns][3] *= a1;
            }
        }
#pragma unroll
        for (int k8 = 0; k8 < 64; k8 += 8) {
            uint32_t ap[4];
            ap[0] = f2tf32(Ss[(mrow0)     * SSTR + k8 + tg]);
            ap[1] = f2tf32(Ss[(mrow0 + 8) * SSTR + k8 + tg]);
            ap[2] = f2tf32(Ss[(mrow0)     * SSTR + k8 + tg + 4]);
            ap[3] = f2tf32(Ss[(mrow0 + 8) * SSTR + k8 + tg + 4]);
#pragma unroll
            for (int ns = 0; ns < 8; ns++) {
                const int c = nj * 64 + ns * 8 + g;
                float v0 = KVs[(k8 + tg)     * VSTR + c];
                float v1 = KVs[(k8 + tg + 4) * VSTR + c];
                uint32_t bh[2], bl[2];
                bh[0] = f2tf32(v0);
                bh[1] = f2tf32(v1);
                bl[0] = f2tf32(v0 - __uint_as_float(bh[0]));
                bl[1] = f2tf32(v1 - __uint_as_float(bh[1]));
                mma_tf32(accO[ns], ap, bh);
                mma_tf32(accO[ns], ap, bl);
            }
        }
        __syncthreads();
    }

    // ---- epilogue: normalize + store ----
    const float inv0 = 1.f / lrow[mrow0];
    const float inv1 = 1.f / lrow[mrow0 + 8];
#pragma unroll
    for (int ns = 0; ns < 8; ns++) {
        const int cc = h * HD + nj * 64 + ns * 8 + 2 * tg;
        float* op0 = O + (size_t)(qb * 64 + mrow0) * QD + cc;
        float* op1 = O + (size_t)(qb * 64 + mrow0 + 8) * QD + cc;
        *(float2*)op0 = make_float2(accO[ns][0] * inv0, accO[ns][1] * inv0);
        *(float2*)op1 = make_float2(accO[ns][2] * inv1, accO[ns][3] * inv1);
    }
}

// ---------------------------------------------------------------------------
// Launch
// ---------------------------------------------------------------------------
extern "C" void kernel_launch(void* const* d_in, const int* in_sizes, int n_in,
                              void* d_out, int out_size)
{
    (void)in_sizes; (void)n_in; (void)out_size;
    const float* x  = (const float*)d_in[0];
    const float* wq = (const float*)d_in[1];
    const float* wk = (const float*)d_in[2];
    const float* wv = (const float*)d_in[3];
    const float* wo = (const float*)d_in[4];
    const float* fc = (const float*)d_in[5];
    const float* fs = (const float*)d_in[6];
    float* out = (float*)d_out;

    float *q, *k, *v, *att;
    cudaGetSymbolAddress((void**)&q,   g_q);
    cudaGetSymbolAddress((void**)&k,   g_k);
    cudaGetSymbolAddress((void**)&v,   g_v);
    cudaGetSymbolAddress((void**)&att, g_att);

    cudaFuncSetAttribute(gemm_tf32,
                         cudaFuncAttributeMaxDynamicSharedMemorySize,
                         GEMM_SMEM_BYTES);
    cudaFuncSetAttribute(flash_attn_tc,
                         cudaFuncAttributeMaxDynamicSharedMemorySize,
                         FA_SMEM_BYTES);

    // QKV projections (tf32 tensor cores)
    gemm_tf32<<<dim3(QD / BN,  SEQ / BM), 256, GEMM_SMEM_BYTES>>>(x, wq, q, SEQ, QD,  DIMM);
    gemm_tf32<<<dim3(KVD / BN, SEQ / BM), 256, GEMM_SMEM_BYTES>>>(x, wk, k, SEQ, KVD, DIMM);
    gemm_tf32<<<dim3(KVD / BN, SEQ / BM), 256, GEMM_SMEM_BYTES>>>(x, wv, v, SEQ, KVD, DIMM);

    // RoPE
    int totq = SEQ * NHEADS * (HD / 2);
    int totk = SEQ * NKVH * (HD / 2);
    rope_kernel<<<(totq + 255) / 256, 256>>>(q, fc, fs, NHEADS, totq);
    rope_kernel<<<(totk + 255) / 256, 256>>>(k, fc, fs, NKVH, totk);

    // Fused causal attention (tensor cores)
    flash_attn_tc<<<dim3(SEQ / 64, NHEADS), 256, FA_SMEM_BYTES>>>(q, k, v, att);

    // Output projection
    gemm_tf32<<<dim3(DIMM / BN, SEQ / BM), 256, GEMM_SMEM_BYTES>>>(att, wo, out, SEQ, DIMM, QD);
}

// round 7
// speedup vs baseline: 3.0840x; 1.0140x over previous
#include <cuda_runtime.h>
#include <cstdint>

#define SEQ    2048
#define DIMM   4096
#define NHEADS 32
#define NKVH   8
#define HD     128
#define QD     (NHEADS * HD)   // 4096
#define KVD    (NKVH * HD)     // 1024

// Scratch (no cudaMalloc allowed)
__device__ float g_q[SEQ * QD];
__device__ float g_k[SEQ * KVD];
__device__ float g_v[SEQ * KVD];
__device__ float g_att[SEQ * QD];

__device__ __forceinline__ uint32_t f2tf32(float x) {
    uint32_t r;
    asm("cvt.rna.tf32.f32 %0, %1;" : "=r"(r) : "f"(x));
    return r;
}

__device__ __forceinline__ void mma_tf32(float* c, const uint32_t* a, const uint32_t* b) {
    asm volatile(
        "mma.sync.aligned.m16n8k8.row.col.f32.tf32.tf32.f32 "
        "{%0,%1,%2,%3}, {%4,%5,%6,%7}, {%8,%9}, {%0,%1,%2,%3};\n"
        : "+f"(c[0]), "+f"(c[1]), "+f"(c[2]), "+f"(c[3])
        : "r"(a[0]), "r"(a[1]), "r"(a[2]), "r"(a[3]),
          "r"(b[0]), "r"(b[1]));
}

__device__ __forceinline__ void cp_async16(void* smem_dst, const void* gmem_src) {
    uint32_t dst = (uint32_t)__cvta_generic_to_shared(smem_dst);
    asm volatile("cp.async.cg.shared.global [%0], [%1], 16;\n"
                 :: "r"(dst), "l"(gmem_src));
}
__device__ __forceinline__ void cp_commit() {
    asm volatile("cp.async.commit_group;\n");
}
__device__ __forceinline__ void cp_wait0() {
    asm volatile("cp.async.wait_group 0;\n");
}

// ===========================================================================
// TF32 tensor-core GEMM — 4-stage cp.async ring (wait_group 2)
// ===========================================================================
#define BM 128
#define BN 128
#define BK 32
#define ASTRIDE 36
#define BSTRIDE 136
#define STAGE_FLOATS (BM * ASTRIDE + BK * BSTRIDE)   // 8960
#define NSTAGE 4
#define GEMM_SMEM_BYTES (NSTAGE * STAGE_FLOATS * 4)  // 143360

__global__ __launch_bounds__(256, 1) void gemm_tf32(
    const float* __restrict__ A, const float* __restrict__ B,
    float* __restrict__ C, int M, int N, int K)
{
    extern __shared__ float sm[];

    const int tid = threadIdx.x;
    const int bx = blockIdx.x, by = blockIdx.y;

    const int arow0 = tid >> 3;
    const int acol4 = (tid & 7) << 2;
    const int brow0 = tid >> 5;
    const int bcol4 = (tid & 31) << 2;

    const int lane = tid & 31;
    const int warp = tid >> 5;
    const int wr = warp >> 2;
    const int wc = warp & 3;
    const int g  = lane >> 2;
    const int tg = lane & 3;
    const int morg = wr * 64;
    const int norg = wc * 32;

    const float* Ab = A + (size_t)by * BM * K;
    const float* Bb = B + (size_t)bx * BN;

    float acc[4][4][4];
#pragma unroll
    for (int mi = 0; mi < 4; mi++)
#pragma unroll
        for (int ni = 0; ni < 4; ni++)
#pragma unroll
            for (int r = 0; r < 4; r++) acc[mi][ni][r] = 0.f;

    const int nk = K / BK;

    auto load_stage = [&](int s, int k0) {
        float* As_ = sm + s * STAGE_FLOATS;
        float* Bs_ = As_ + BM * ASTRIDE;
#pragma unroll
        for (int r = 0; r < BM; r += 32)
            cp_async16(&As_[(arow0 + r) * ASTRIDE + acol4],
                       Ab + (size_t)(arow0 + r) * K + k0 + acol4);
#pragma unroll
        for (int r = 0; r < BK; r += 8)
            cp_async16(&Bs_[(brow0 + r) * BSTRIDE + bcol4],
                       Bb + (size_t)(k0 + brow0 + r) * N + bcol4);
        cp_commit();
    };

    // prologue: 3 stages in flight
    load_stage(0, 0);
    load_stage(1, BK);
    load_stage(2, 2 * BK);

    for (int kt = 0; kt < nk; kt++) {
        asm volatile("cp.async.wait_group 2;\n");
        __syncthreads();
        // one commit per iteration keeps group accounting uniform
        if (kt + 3 < nk) load_stage((kt + 3) & (NSTAGE - 1), (kt + 3) * BK);
        else             cp_commit();   // empty group

        const float* As_ = sm + (kt & (NSTAGE - 1)) * STAGE_FLOATS;
        const float* Bs_ = As_ + BM * ASTRIDE;

#pragma unroll
        for (int k8 = 0; k8 < BK; k8 += 8) {
            uint32_t af[4][4], bf[4][2];
#pragma unroll
            for (int mi = 0; mi < 4; mi++) {
                const int r = morg + mi * 16 + g;
                af[mi][0] = f2tf32(As_[(r)     * ASTRIDE + k8 + tg]);
                af[mi][1] = f2tf32(As_[(r + 8) * ASTRIDE + k8 + tg]);
                af[mi][2] = f2tf32(As_[(r)     * ASTRIDE + k8 + tg + 4]);
                af[mi][3] = f2tf32(As_[(r + 8) * ASTRIDE + k8 + tg + 4]);
            }
#pragma unroll
            for (int ni = 0; ni < 4; ni++) {
                const int c = norg + ni * 8 + g;
                bf[ni][0] = f2tf32(Bs_[(k8 + tg)     * BSTRIDE + c]);
                bf[ni][1] = f2tf32(Bs_[(k8 + tg + 4) * BSTRIDE + c]);
            }
#pragma unroll
            for (int mi = 0; mi < 4; mi++)
#pragma unroll
                for (int ni = 0; ni < 4; ni++)
                    mma_tf32(acc[mi][ni], af[mi], bf[ni]);
        }
    }

    float* Cb = C + (size_t)(by * BM) * N + bx * BN;
#pragma unroll
    for (int mi = 0; mi < 4; mi++) {
#pragma unroll
        for (int ni = 0; ni < 4; ni++) {
            const int r0 = morg + mi * 16 + g;
            const int c0 = norg + ni * 8 + tg * 2;
            *(float2*)(&Cb[(size_t)r0 * N + c0]) =
                make_float2(acc[mi][ni][0], acc[mi][ni][1]);
            *(float2*)(&Cb[(size_t)(r0 + 8) * N + c0]) =
                make_float2(acc[mi][ni][2], acc[mi][ni][3]);
        }
    }
}

// ---------------------------------------------------------------------------
// RoPE (interleaved pairs)
// ---------------------------------------------------------------------------
__global__ void rope_kernel(float* __restrict__ t,
                            const float* __restrict__ fc,
                            const float* __restrict__ fs,
                            int nheads, int total)
{
    int idx = blockIdx.x * blockDim.x + threadIdx.x;
    if (idx >= total) return;
    int p = idx & 63;
    int h = (idx >> 6) % nheads;
    int s = idx / (64 * nheads);
    float c  = fc[s * 64 + p];
    float sn = fs[s * 64 + p];
    float* base = t + (size_t)s * nheads * HD + h * HD + 2 * p;
    float re = base[0], im = base[1];
    base[0] = re * c - im * sn;
    base[1] = re * sn + im * c;
}

// ===========================================================================
// Tensor-core flash attention (causal, GQA 4:1).
// QK^T tf32; P@V with exact bitmask hi/lo V split (2 tf32 mma).
// Softmax parallel over all 256 threads (4/row, butterfly shuffles).
// K/V tiles filled via cp.async (V copy overlaps softmax).
// ===========================================================================
#define QSTR 132
#define VSTR 136
#define SSTR 68
#define FA_Q_FLOATS   (64 * QSTR)
#define FA_KV_FLOATS  (64 * VSTR)
#define FA_S_FLOATS   (64 * SSTR)
#define FA_SMEM_FLOATS (FA_Q_FLOATS + FA_KV_FLOATS + FA_S_FLOATS + 192)
#define FA_SMEM_BYTES  (FA_SMEM_FLOATS * 4)   // 86784

__global__ __launch_bounds__(256, 2) void flash_attn_tc(
    const float* __restrict__ Q, const float* __restrict__ K,
    const float* __restrict__ V, float* __restrict__ O)
{
    extern __shared__ float sm[];
    float* Qt   = sm;                          // [64][QSTR]
    float* KVs  = sm + FA_Q_FLOATS;            // K:[64][QSTR] or V:[64][VSTR]
    float* Ss   = KVs + FA_KV_FLOATS;          // [64][SSTR]
    float* mrow = Ss + FA_S_FLOATS;
    float* lrow = mrow + 64;
    float* arow = lrow + 64;

    const int tid  = threadIdx.x;
    const int qb   = blockIdx.x, h = blockIdx.y, kvh = h >> 2;
    const int lane = tid & 31;
    const int warp = tid >> 5;
    const int g    = lane >> 2;
    const int tg   = lane & 3;
    const int mi   = warp & 3;
    const int nj   = warp >> 2;
    const int lr   = tid >> 5;
    const int ld4  = (tid & 31) << 2;
    const float scale = 0.08838834764831845f;

    const int mrow0 = mi * 16 + g;

    // softmax mapping: 4 threads per row
    const int sr = tid >> 2;          // row 0..63
    const int sq = (tid & 3) << 4;    // col base 0,16,32,48

    // ---- load Q tile (prescaled) ----
#pragma unroll
    for (int rr = 0; rr < 64; rr += 8) {
        float4 v = *(const float4*)(Q + (size_t)(qb * 64 + lr + rr) * QD + h * HD + ld4);
        v.x *= scale; v.y *= scale; v.z *= scale; v.w *= scale;
        *(float4*)(Qt + (lr + rr) * QSTR + ld4) = v;
    }
    if (tid < 64) { mrow[tid] = -1e30f; lrow[tid] = 0.f; }

    float accO[8][4];
#pragma unroll
    for (int ns = 0; ns < 8; ns++)
#pragma unroll
        for (int r = 0; r < 4; r++) accO[ns][r] = 0.f;

    // first K tile via cp.async
#pragma unroll
    for (int rr = 0; rr < 64; rr += 8)
        cp_async16(KVs + (lr + rr) * QSTR + ld4,
                   K + (size_t)(0 * 64 + lr + rr) * KVD + kvh * HD + ld4);
    cp_commit();
    cp_wait0();
    __syncthreads();

    for (int kb = 0; kb <= qb; kb++) {
        // ---- S = Qs @ K^T : warp tile 16x32 at (mi*16, nj*32) ----
        float cS[4][4];
#pragma unroll
        for (int ns = 0; ns < 4; ns++)
#pragma unroll
            for (int r = 0; r < 4; r++) cS[ns][r] = 0.f;

#pragma unroll
        for (int k8 = 0; k8 < HD; k8 += 8) {
            uint32_t a[4];
            a[0] = f2tf32(Qt[(mrow0)     * QSTR + k8 + tg]);
            a[1] = f2tf32(Qt[(mrow0 + 8) * QSTR + k8 + tg]);
            a[2] = f2tf32(Qt[(mrow0)     * QSTR + k8 + tg + 4]);
            a[3] = f2tf32(Qt[(mrow0 + 8) * QSTR + k8 + tg + 4]);
#pragma unroll
            for (int ns = 0; ns < 4; ns++) {
                const int c = nj * 32 + ns * 8 + g;
                uint32_t b[2];
                b[0] = f2tf32(KVs[c * QSTR + k8 + tg]);
                b[1] = f2tf32(KVs[c * QSTR + k8 + tg + 4]);
                mma_tf32(cS[ns], a, b);
            }
        }
#pragma unroll
        for (int ns = 0; ns < 4; ns++) {
            const int cc = nj * 32 + ns * 8 + 2 * tg;
            *(float2*)(Ss + (mrow0)     * SSTR + cc) = make_float2(cS[ns][0], cS[ns][1]);
            *(float2*)(Ss + (mrow0 + 8) * SSTR + cc) = make_float2(cS[ns][2], cS[ns][3]);
        }
        __syncthreads();   // S visible; all K reads done

        // ---- V tile via cp.async (overlaps softmax) ----
#pragma unroll
        for (int rr = 0; rr < 64; rr += 8)
            cp_async16(KVs + (lr + rr) * VSTR + ld4,
                       V + (size_t)(kb * 64 + lr + rr) * KVD + kvh * HD + ld4);
        cp_commit();

        // ---- softmax: 4 threads per row ----
        {
            const int lim = (kb == qb) ? (sr + 1) : 64;
            float* srow = Ss + sr * SSTR + sq;
            float4 s0 = *(float4*)(srow);
            float4 s1 = *(float4*)(srow + 4);
            float4 s2 = *(float4*)(srow + 8);
            float4 s3 = *(float4*)(srow + 12);
            float sv[16] = {s0.x,s0.y,s0.z,s0.w, s1.x,s1.y,s1.z,s1.w,
                            s2.x,s2.y,s2.z,s2.w, s3.x,s3.y,s3.z,s3.w};
            float mx = -1e30f;
#pragma unroll
            for (int c = 0; c < 16; c++)
                if (sq + c < lim) mx = fmaxf(mx, sv[c]);
            mx = fmaxf(mx, __shfl_xor_sync(0xffffffffu, mx, 1));
            mx = fmaxf(mx, __shfl_xor_sync(0xffffffffu, mx, 2));
            float mold = mrow[sr];
            mx = fmaxf(mx, mold);
            float sum = 0.f;
#pragma unroll
            for (int c = 0; c < 16; c++) {
                float p = (sq + c < lim) ? __expf(sv[c] - mx) : 0.f;
                sv[c] = p;
                sum += p;
            }
            sum += __shfl_xor_sync(0xffffffffu, sum, 1);
            sum += __shfl_xor_sync(0xffffffffu, sum, 2);
            *(float4*)(srow)      = make_float4(sv[0],  sv[1],  sv[2],  sv[3]);
            *(float4*)(srow + 4)  = make_float4(sv[4],  sv[5],  sv[6],  sv[7]);
            *(float4*)(srow + 8)  = make_float4(sv[8],  sv[9],  sv[10], sv[11]);
            *(float4*)(srow + 12) = make_float4(sv[12], sv[13], sv[14], sv[15]);
            if ((tid & 3) == 0) {
                float alpha = __expf(mold - mx);
                mrow[sr] = mx;
                lrow[sr] = lrow[sr] * alpha + sum;
                arow[sr] = alpha;
            }
        }
        cp_wait0();        // own V copies landed
        __syncthreads();   // everyone's V + P + arow visible

        // ---- O = O*alpha + P @ V (exact bitmask hi/lo split of V) ----
        {
            float a0 = arow[mrow0], a1 = arow[mrow0 + 8];
#pragma unroll
            for (int ns = 0; ns < 8; ns++) {
                accO[ns][0] *= a0; accO[ns][1] *= a0;
                accO[ns][2] *= a1; accO[ns][3] *= a1;
            }
        }
#pragma unroll
        for (int k8 = 0; k8 < 64; k8 += 8) {
            uint32_t ap[4];
            ap[0] = f2tf32(Ss[(mrow0)     * SSTR + k8 + tg]);
            ap[1] = f2tf32(Ss[(mrow0 + 8) * SSTR + k8 + tg]);
            ap[2] = f2tf32(Ss[(mrow0)     * SSTR + k8 + tg + 4]);
            ap[3] = f2tf32(Ss[(mrow0 + 8) * SSTR + k8 + tg + 4]);
#pragma unroll
            for (int ns = 0; ns < 8; ns++) {
                const int c = nj * 64 + ns * 8 + g;
                float v0 = KVs[(k8 + tg)     * VSTR + c];
                float v1 = KVs[(k8 + tg + 4) * VSTR + c];
                uint32_t bh[2], bl[2];
                bh[0] = __float_as_uint(v0) & 0xffffe000u;    // ALU pipe
                bh[1] = __float_as_uint(v1) & 0xffffe000u;
                bl[0] = __float_as_uint(v0 - __uint_as_float(bh[0]));  // exact
                bl[1] = __float_as_uint(v1 - __uint_as_float(bh[1]));
                mma_tf32(accO[ns], ap, bh);
                mma_tf32(accO[ns], ap, bl);
            }
        }
        __syncthreads();   // PV done; KVs free

        // ---- next K tile via cp.async ----
        if (kb + 1 <= qb) {
#pragma unroll
            for (int rr = 0; rr < 64; rr += 8)
                cp_async16(KVs + (lr + rr) * QSTR + ld4,
                           K + (size_t)((kb + 1) * 64 + lr + rr) * KVD + kvh * HD + ld4);
            cp_commit();
            cp_wait0();
            __syncthreads();
        }
    }

    // ---- epilogue ----
    const float inv0 = 1.f / lrow[mrow0];
    const float inv1 = 1.f / lrow[mrow0 + 8];
#pragma unroll
    for (int ns = 0; ns < 8; ns++) {
        const int cc = h * HD + nj * 64 + ns * 8 + 2 * tg;
        float* op0 = O + (size_t)(qb * 64 + mrow0) * QD + cc;
        float* op1 = O + (size_t)(qb * 64 + mrow0 + 8) * QD + cc;
        *(float2*)op0 = make_float2(accO[ns][0] * inv0, accO[ns][1] * inv0);
        *(float2*)op1 = make_float2(accO[ns][2] * inv1, accO[ns][3] * inv1);
    }
}

// ---------------------------------------------------------------------------
// Launch
// ---------------------------------------------------------------------------
extern "C" void kernel_launch(void* const* d_in, const int* in_sizes, int n_in,
                              void* d_out, int out_size)
{
    (void)in_sizes; (void)n_in; (void)out_size;
    const float* x  = (const float*)d_in[0];
    const float* wq = (const float*)d_in[1];
    const float* wk = (const float*)d_in[2];
    const float* wv = (const float*)d_in[3];
    const float* wo = (const float*)d_in[4];
    const float* fc = (const float*)d_in[5];
    const float* fs = (const float*)d_in[6];
    float* out = (float*)d_out;

    float *q, *k, *v, *att;
    cudaGetSymbolAddress((void**)&q,   g_q);
    cudaGetSymbolAddress((void**)&k,   g_k);
    cudaGetSymbolAddress((void**)&v,   g_v);
    cudaGetSymbolAddress((void**)&att, g_att);

    cudaFuncSetAttribute(gemm_tf32,
                         cudaFuncAttributeMaxDynamicSharedMemorySize,
                         GEMM_SMEM_BYTES);
    cudaFuncSetAttribute(flash_attn_tc,
                         cudaFuncAttributeMaxDynamicSharedMemorySize,
                         FA_SMEM_BYTES);

    // QKV projections (tf32 tensor cores)
    gemm_tf32<<<dim3(QD / BN,  SEQ / BM), 256, GEMM_SMEM_BYTES>>>(x, wq, q, SEQ, QD,  DIMM);
    gemm_tf32<<<dim3(KVD / BN, SEQ / BM), 256, GEMM_SMEM_BYTES>>>(x, wk, k, SEQ, KVD, DIMM);
    gemm_tf32<<<dim3(KVD / BN, SEQ / BM), 256, GEMM_SMEM_BYTES>>>(x, wv, v, SEQ, KVD, DIMM);

    // RoPE
    int totq = SEQ * NHEADS * (HD / 2);
    int totk = SEQ * NKVH * (HD / 2);
    rope_kernel<<<(totq + 255) / 256, 256>>>(q, fc, fs, NHEADS, totq);
    rope_kernel<<<(totk + 255) / 256, 256>>>(k, fc, fs, NKVH, totk);

    // Fused causal attention (tensor cores)
    flash_attn_tc<<<dim3(SEQ / 64, NHEADS), 256, FA_SMEM_BYTES>>>(q, k, v, att);

    // Output projection
    gemm_tf32<<<dim3(DIMM / BN, SEQ / BM), 256, GEMM_SMEM_BYTES>>>(att, wo, out, SEQ, DIMM, QD);
}